// round 5
// baseline (speedup 1.0000x reference)
#include <cuda_runtime.h>
#include <math.h>

#define T_STEPS 512
#define B_DIM   64
#define DIN     1024
#define DH      1024
#define BN_EPS  1e-5f

#define NCTA        128
#define COLS_PER_CTA 8     // 1024 / 128
#define NTHREADS    256

// ---------------- scratch (no cudaMalloc allowed) ----------------
__device__ float g_xp[(size_t)T_STEPS * B_DIM * DH];   // [t][b][j]  (x@Wx + b)
__device__ float g_stateT[2][DH * B_DIM];              // [j][b] transposed state, double buffered
__device__ unsigned int g_bar_count = 0;
__device__ volatile unsigned int g_bar_gen = 0;

// ---------------- software grid barrier (all CTAs resident) ----------------
__device__ __forceinline__ void grid_barrier(unsigned int nblocks) {
    __syncthreads();
    if (threadIdx.x == 0) {
        __threadfence();                       // release my CTA's global writes
        unsigned int gen = g_bar_gen;
        if (atomicAdd(&g_bar_count, 1u) == nblocks - 1u) {
            atomicExch(&g_bar_count, 0u);
            __threadfence();
            g_bar_gen = gen + 1u;
        } else {
            while (g_bar_gen == gen) { }
        }
        __threadfence();                       // acquire
    }
    __syncthreads();
}

// ---------------- kernel 1: XP = X @ Wx + b  (M=32768, N=1024, K=1024) ----------------
#define GM_BM 128
#define GM_BN 128
#define GM_BK 8
#define GM_TM 8
#define GM_TN 8

__global__ void __launch_bounds__(256) xw_gemm_kernel(
    const float* __restrict__ X,    // [M][K]
    const float* __restrict__ Wx,   // [K][N]
    const float* __restrict__ bias, // [N]
    float* __restrict__ XP)         // [M][N]
{
    __shared__ float As[GM_BK][GM_BM];
    __shared__ float Bs[GM_BK][GM_BN];

    const int K = DIN, N = DH;
    const int bx = blockIdx.x;   // N tile
    const int by = blockIdx.y;   // M tile
    const int tid = threadIdx.x;

    // A tile load: 128x8 -> one float4 along K per thread
    const int a_row = tid >> 1;
    const int a_col = (tid & 1) * 4;
    // B tile load: 8x128 -> one float4 along N per thread
    const int b_row = tid >> 5;
    const int b_col = (tid & 31) * 4;

    const int tr = tid / 16;     // 0..15
    const int tc = tid % 16;     // 0..15

    float acc[GM_TM][GM_TN];
#pragma unroll
    for (int i = 0; i < GM_TM; i++)
#pragma unroll
        for (int j = 0; j < GM_TN; j++) acc[i][j] = 0.0f;

    const float* Aptr = X + (size_t)(by * GM_BM) * K;
    const float* Bptr = Wx + bx * GM_BN;

    for (int k0 = 0; k0 < K; k0 += GM_BK) {
        float4 av = *(const float4*)(Aptr + (size_t)a_row * K + k0 + a_col);
        As[a_col + 0][a_row] = av.x;
        As[a_col + 1][a_row] = av.y;
        As[a_col + 2][a_row] = av.z;
        As[a_col + 3][a_row] = av.w;
        float4 bv = *(const float4*)(Bptr + (size_t)(k0 + b_row) * N + b_col);
        *(float4*)&Bs[b_row][b_col] = bv;
        __syncthreads();

#pragma unroll
        for (int k = 0; k < GM_BK; k++) {
            float ra[GM_TM], rb[GM_TN];
#pragma unroll
            for (int i = 0; i < GM_TM; i++) ra[i] = As[k][tr * GM_TM + i];
#pragma unroll
            for (int j = 0; j < GM_TN; j++) rb[j] = Bs[k][tc * GM_TN + j];
#pragma unroll
            for (int i = 0; i < GM_TM; i++)
#pragma unroll
                for (int j = 0; j < GM_TN; j++)
                    acc[i][j] += ra[i] * rb[j];
        }
        __syncthreads();
    }

    // epilogue: add bias, write
#pragma unroll
    for (int i = 0; i < GM_TM; i++) {
        int row = by * GM_BM + tr * GM_TM + i;
#pragma unroll
        for (int j = 0; j < GM_TN; j += 4) {
            int col = bx * GM_BN + tc * GM_TN + j;
            float4 v;
            v.x = acc[i][j + 0] + bias[col + 0];
            v.y = acc[i][j + 1] + bias[col + 1];
            v.z = acc[i][j + 2] + bias[col + 2];
            v.w = acc[i][j + 3] + bias[col + 3];
            *(float4*)(XP + (size_t)row * N + col) = v;
        }
    }
}

// ---------------- kernel 2: persistent recurrent loop ----------------
__global__ void __launch_bounds__(NTHREADS) rnn_persistent_kernel(
    const float* __restrict__ state0,  // [1][B][DH]  (b-major)
    const float* __restrict__ Wh,      // [DH][DH]  (k-major rows)
    float* __restrict__ out,           // [2*T*B*DH] or [T*B*DH]
    int out_elems)
{
    __shared__ float s_part[8 * 512];   // per-warp split-K partials
    __shared__ float s_h[512];          // h then s, layout o = b*8 + jj

    const int cta  = blockIdx.x;
    const int tid  = threadIdx.x;
    const int warp = tid >> 5;
    const int lane = tid & 31;
    const int j0   = cta * COLS_PER_CTA;

    // init transposed state buffer 0 for our columns
    for (int o = tid; o < 512; o += NTHREADS) {
        int jj = o >> 6;
        int b  = o & 63;
        g_stateT[0][(j0 + jj) * B_DIM + b] = state0[(size_t)b * DH + j0 + jj];
    }

    const long long half = (long long)T_STEPS * B_DIM * DH;
    const bool dup = ((long long)out_elems >= 2 * half);

    for (int t = 0; t < T_STEPS; t++) {
        grid_barrier(NCTA);   // previous step's state writes (and init) visible

        const float* st  = g_stateT[t & 1];
        float*       stn = g_stateT[(t + 1) & 1];

        // ---- recurrent GEMM: acc[jj][bb] = sum_k st[k][2*lane+bb] * Wh[k][j0+jj]
        float acc[8][2];
#pragma unroll
        for (int j = 0; j < 8; j++) { acc[j][0] = 0.0f; acc[j][1] = 0.0f; }

        const int b0 = lane * 2;
        const int k0 = warp * 128;
#pragma unroll 4
        for (int k = k0; k < k0 + 128; k++) {
            // state is rewritten every step by other SMs -> bypass L1
            float2 sv = __ldcg((const float2*)(st + (size_t)k * B_DIM + b0));
            float4 wA = __ldg((const float4*)(Wh + (size_t)k * DH + j0));
            float4 wB = __ldg((const float4*)(Wh + (size_t)k * DH + j0 + 4));
            acc[0][0] += wA.x * sv.x;  acc[0][1] += wA.x * sv.y;
            acc[1][0] += wA.y * sv.x;  acc[1][1] += wA.y * sv.y;
            acc[2][0] += wA.z * sv.x;  acc[2][1] += wA.z * sv.y;
            acc[3][0] += wA.w * sv.x;  acc[3][1] += wA.w * sv.y;
            acc[4][0] += wB.x * sv.x;  acc[4][1] += wB.x * sv.y;
            acc[5][0] += wB.y * sv.x;  acc[5][1] += wB.y * sv.y;
            acc[6][0] += wB.z * sv.x;  acc[6][1] += wB.z * sv.y;
            acc[7][0] += wB.w * sv.x;  acc[7][1] += wB.w * sv.y;
        }

        // store partials: s_part[warp*512 + lane*16 + jj*2 + bb]
        {
            float4* dst = (float4*)&s_part[warp * 512 + lane * 16];
            const float4* srcv = (const float4*)acc;
#pragma unroll
            for (int q = 0; q < 4; q++) dst[q] = srcv[q];
        }
        __syncthreads();

        // ---- split-K reduce + XP + tanh : o = b*8 + jj
        const float* xp_t = g_xp + (size_t)t * B_DIM * DH;
#pragma unroll
        for (int rep = 0; rep < 2; rep++) {
            int o  = tid + rep * 256;
            int jj = o & 7;
            int b  = o >> 3;
            float z = xp_t[(size_t)b * DH + j0 + jj];
            int pi = (b >> 1) * 16 + jj * 2 + (b & 1);
#pragma unroll
            for (int w = 0; w < 8; w++) z += s_part[w * 512 + pi];
            s_h[o] = tanhf(z);
        }
        __syncthreads();

        // ---- BatchNorm over batch dim: warp jj handles column j0+jj
        {
            int jj = warp;
            float v1 = s_h[lane * 8 + jj];
            float v2 = s_h[(lane + 32) * 8 + jj];
            float sm = v1 + v2;
            float sq = v1 * v1 + v2 * v2;
#pragma unroll
            for (int off = 16; off; off >>= 1) {
                sm += __shfl_xor_sync(0xFFFFFFFFu, sm, off);
                sq += __shfl_xor_sync(0xFFFFFFFFu, sq, off);
            }
            float mu   = sm * (1.0f / 64.0f);
            float var  = sq * (1.0f / 64.0f) - mu * mu;
            float rstd = rsqrtf(var + BN_EPS);
            float o1 = (v1 - mu) * rstd;
            float o2 = (v2 - mu) * rstd;
            // next state (transposed, coalesced per column)
            stn[(j0 + jj) * B_DIM + lane]      = o1;
            stn[(j0 + jj) * B_DIM + lane + 32] = o2;
            // keep normalized value for the output writer
            s_h[lane * 8 + jj]        = o1;
            s_h[(lane + 32) * 8 + jj] = o2;
        }
        __syncthreads();

        // ---- write outputs (both tuple copies), 32B-coalesced in j
        float* ob  = out + (size_t)t * B_DIM * DH;
        float* ob2 = out + half + (size_t)t * B_DIM * DH;
#pragma unroll
        for (int rep = 0; rep < 2; rep++) {
            int o  = tid + rep * 256;
            int jj = o & 7;
            int b  = o >> 3;
            float v = s_h[o];
            size_t idx = (size_t)b * DH + j0 + jj;
            ob[idx] = v;
            if (dup) ob2[idx] = v;
        }
    }
}

// ---------------- launch ----------------
extern "C" void kernel_launch(void* const* d_in, const int* in_sizes, int n_in,
                              void* d_out, int out_size) {
    const float* x      = (const float*)d_in[0];  // [T][B][DIN]
    const float* state0 = (const float*)d_in[1];  // [1][B][DH]
    const float* Wx     = (const float*)d_in[2];  // [DIN][DH]
    const float* Wh     = (const float*)d_in[3];  // [DH][DH]
    const float* bias   = (const float*)d_in[4];  // [DH]
    float* out = (float*)d_out;

    // XP = X @ Wx + bias
    {
        float* xp;
        cudaGetSymbolAddress((void**)&xp, g_xp);
        dim3 grid(DH / GM_BN, (T_STEPS * B_DIM) / GM_BM);
        xw_gemm_kernel<<<grid, 256>>>(x, Wx, bias, xp);
    }
    // persistent recurrence
    rnn_persistent_kernel<<<NCTA, NTHREADS>>>(state0, Wh, out, out_size);
}

// round 6
// speedup vs baseline: 2.3649x; 2.3649x over previous
#include <cuda_runtime.h>
#include <math.h>

#define T_STEPS 512
#define B_DIM   64
#define DIN     1024
#define DH      1024
#define BN_EPS  1e-5f

#define NCTA        128
#define COLS_PER_CTA 8     // 1024 / 128
#define NTHREADS    512
#define NWARPS      16     // NTHREADS / 32
#define K_PER_WARP  64     // DH / NWARPS

// dynamic smem layout (floats):
//   s_wh   [DH * 8]      = 8192   (weight slab for this CTA's 8 columns)
//   s_part [NWARPS * 512]= 8192   (split-K partials)
//   s_h    [512]                  (h / normalized values)
#define SMEM_FLOATS (8192 + 8192 + 512)
#define SMEM_BYTES  (SMEM_FLOATS * 4)

// ---------------- scratch (no cudaMalloc allowed) ----------------
__device__ float g_xp[(size_t)T_STEPS * B_DIM * DH];   // [t][b][j]  (x@Wx + b)
__device__ float g_stateT[2][DH * B_DIM];              // [j][b] transposed state, double buffered
__device__ unsigned int g_bar_count = 0;
__device__ volatile unsigned int g_bar_gen = 0;

// ---------------- software grid barrier (all CTAs resident) ----------------
__device__ __forceinline__ void grid_barrier(unsigned int nblocks) {
    __syncthreads();
    if (threadIdx.x == 0) {
        __threadfence();                       // release my CTA's global writes
        unsigned int gen = g_bar_gen;
        if (atomicAdd(&g_bar_count, 1u) == nblocks - 1u) {
            atomicExch(&g_bar_count, 0u);
            __threadfence();
            g_bar_gen = gen + 1u;
        } else {
            while (g_bar_gen == gen) { }
        }
        __threadfence();                       // acquire
    }
    __syncthreads();
}

// ---------------- kernel 1: XP = X @ Wx + b  (M=32768, N=1024, K=1024) ----------------
#define GM_BM 128
#define GM_BN 128
#define GM_BK 8
#define GM_TM 8
#define GM_TN 8

__global__ void __launch_bounds__(256) xw_gemm_kernel(
    const float* __restrict__ X,    // [M][K]
    const float* __restrict__ Wx,   // [K][N]
    const float* __restrict__ bias, // [N]
    float* __restrict__ XP)         // [M][N]
{
    __shared__ float As[GM_BK][GM_BM];
    __shared__ float Bs[GM_BK][GM_BN];

    const int K = DIN, N = DH;
    const int bx = blockIdx.x;   // N tile
    const int by = blockIdx.y;   // M tile
    const int tid = threadIdx.x;

    const int a_row = tid >> 1;
    const int a_col = (tid & 1) * 4;
    const int b_row = tid >> 5;
    const int b_col = (tid & 31) * 4;

    const int tr = tid / 16;     // 0..15
    const int tc = tid % 16;     // 0..15

    float acc[GM_TM][GM_TN];
#pragma unroll
    for (int i = 0; i < GM_TM; i++)
#pragma unroll
        for (int j = 0; j < GM_TN; j++) acc[i][j] = 0.0f;

    const float* Aptr = X + (size_t)(by * GM_BM) * K;
    const float* Bptr = Wx + bx * GM_BN;

    for (int k0 = 0; k0 < K; k0 += GM_BK) {
        float4 av = *(const float4*)(Aptr + (size_t)a_row * K + k0 + a_col);
        As[a_col + 0][a_row] = av.x;
        As[a_col + 1][a_row] = av.y;
        As[a_col + 2][a_row] = av.z;
        As[a_col + 3][a_row] = av.w;
        float4 bv = *(const float4*)(Bptr + (size_t)(k0 + b_row) * N + b_col);
        *(float4*)&Bs[b_row][b_col] = bv;
        __syncthreads();

#pragma unroll
        for (int k = 0; k < GM_BK; k++) {
            float ra[GM_TM], rb[GM_TN];
#pragma unroll
            for (int i = 0; i < GM_TM; i++) ra[i] = As[k][tr * GM_TM + i];
#pragma unroll
            for (int j = 0; j < GM_TN; j++) rb[j] = Bs[k][tc * GM_TN + j];
#pragma unroll
            for (int i = 0; i < GM_TM; i++)
#pragma unroll
                for (int j = 0; j < GM_TN; j++)
                    acc[i][j] += ra[i] * rb[j];
        }
        __syncthreads();
    }

#pragma unroll
    for (int i = 0; i < GM_TM; i++) {
        int row = by * GM_BM + tr * GM_TM + i;
#pragma unroll
        for (int j = 0; j < GM_TN; j += 4) {
            int col = bx * GM_BN + tc * GM_TN + j;
            float4 v;
            v.x = acc[i][j + 0] + bias[col + 0];
            v.y = acc[i][j + 1] + bias[col + 1];
            v.z = acc[i][j + 2] + bias[col + 2];
            v.w = acc[i][j + 3] + bias[col + 3];
            *(float4*)(XP + (size_t)row * N + col) = v;
        }
    }
}

// ---------------- kernel 2: persistent recurrent loop ----------------
__global__ void __launch_bounds__(NTHREADS) rnn_persistent_kernel(
    const float* __restrict__ state0,  // [1][B][DH]  (b-major)
    const float* __restrict__ Wh,      // [DH][DH]  (k-major rows)
    float* __restrict__ out,           // [2*T*B*DH] or [T*B*DH]
    int out_elems)
{
    extern __shared__ float smem[];
    float* s_wh   = smem;                 // [DH][8]   8192 floats
    float* s_part = smem + 8192;          // [NWARPS][512]
    float* s_h    = smem + 8192 + 8192;   // [512]

    const int cta  = blockIdx.x;
    const int tid  = threadIdx.x;
    const int warp = tid >> 5;
    const int lane = tid & 31;
    const int j0   = cta * COLS_PER_CTA;

    // ---- stage this CTA's weight slab Wh[:, j0..j0+7] into smem (ONCE) ----
    for (int i = tid; i < 2048; i += NTHREADS) {
        int k = i >> 1;
        int h = (i & 1) * 4;
        *(float4*)&s_wh[k * 8 + h] =
            __ldg((const float4*)(Wh + (size_t)k * DH + j0 + h));
    }

    // init transposed state buffer 0 for our columns
    for (int o = tid; o < 512; o += NTHREADS) {
        int jj = o >> 6;
        int b  = o & 63;
        g_stateT[0][(j0 + jj) * B_DIM + b] = state0[(size_t)b * DH + j0 + jj];
    }

    const long long half = (long long)T_STEPS * B_DIM * DH;
    const bool dup = ((long long)out_elems >= 2 * half);

    for (int t = 0; t < T_STEPS; t++) {
        grid_barrier(NCTA);   // previous step's state writes (and init/weights) visible

        const float* st  = g_stateT[t & 1];
        float*       stn = g_stateT[(t + 1) & 1];

        // ---- recurrent GEMM: acc[jj][bb] = sum_k st[k][2*lane+bb] * Wh[k][j0+jj]
        float acc[8][2];
#pragma unroll
        for (int j = 0; j < 8; j++) { acc[j][0] = 0.0f; acc[j][1] = 0.0f; }

        const int b0 = lane * 2;
        const int k0 = warp * K_PER_WARP;
#pragma unroll 8
        for (int k = k0; k < k0 + K_PER_WARP; k++) {
            // state is rewritten every step by other SMs -> bypass L1
            float2 sv = __ldcg((const float2*)(st + (size_t)k * B_DIM + b0));
            float4 wA = *(const float4*)&s_wh[k * 8];
            float4 wB = *(const float4*)&s_wh[k * 8 + 4];
            acc[0][0] += wA.x * sv.x;  acc[0][1] += wA.x * sv.y;
            acc[1][0] += wA.y * sv.x;  acc[1][1] += wA.y * sv.y;
            acc[2][0] += wA.z * sv.x;  acc[2][1] += wA.z * sv.y;
            acc[3][0] += wA.w * sv.x;  acc[3][1] += wA.w * sv.y;
            acc[4][0] += wB.x * sv.x;  acc[4][1] += wB.x * sv.y;
            acc[5][0] += wB.y * sv.x;  acc[5][1] += wB.y * sv.y;
            acc[6][0] += wB.z * sv.x;  acc[6][1] += wB.z * sv.y;
            acc[7][0] += wB.w * sv.x;  acc[7][1] += wB.w * sv.y;
        }

        // store partials: s_part[warp*512 + lane*16 + jj*2 + bb]
        {
            float4* dst = (float4*)&s_part[warp * 512 + lane * 16];
            const float4* srcv = (const float4*)acc;
#pragma unroll
            for (int q = 0; q < 4; q++) dst[q] = srcv[q];
        }
        __syncthreads();

        // ---- split-K reduce + XP + tanh : o = b*8 + jj  (512 outputs, 512 threads)
        const float* xp_t = g_xp + (size_t)t * B_DIM * DH;
        {
            int o  = tid;
            int jj = o & 7;
            int b  = o >> 3;
            float z = xp_t[(size_t)b * DH + j0 + jj];
            int pi = (b >> 1) * 16 + jj * 2 + (b & 1);
#pragma unroll
            for (int w = 0; w < NWARPS; w++) z += s_part[w * 512 + pi];
            s_h[o] = tanhf(z);
        }
        __syncthreads();

        // ---- BatchNorm over batch dim: warp jj (<8) handles column j0+jj
        if (warp < 8) {
            int jj = warp;
            float v1 = s_h[lane * 8 + jj];
            float v2 = s_h[(lane + 32) * 8 + jj];
            float sm = v1 + v2;
            float sq = v1 * v1 + v2 * v2;
#pragma unroll
            for (int off = 16; off; off >>= 1) {
                sm += __shfl_xor_sync(0xFFFFFFFFu, sm, off);
                sq += __shfl_xor_sync(0xFFFFFFFFu, sq, off);
            }
            float mu   = sm * (1.0f / 64.0f);
            float var  = sq * (1.0f / 64.0f) - mu * mu;
            float rstd = rsqrtf(var + BN_EPS);
            float o1 = (v1 - mu) * rstd;
            float o2 = (v2 - mu) * rstd;
            // next state (transposed, coalesced per column)
            stn[(j0 + jj) * B_DIM + lane]      = o1;
            stn[(j0 + jj) * B_DIM + lane + 32] = o2;
            // keep normalized value for the output writer
            s_h[lane * 8 + jj]        = o1;
            s_h[(lane + 32) * 8 + jj] = o2;
        }
        __syncthreads();

        // ---- write outputs (both tuple copies), coalesced-in-j
        float* ob  = out + (size_t)t * B_DIM * DH;
        float* ob2 = out + half + (size_t)t * B_DIM * DH;
        {
            int o  = tid;
            int jj = o & 7;
            int b  = o >> 3;
            float v = s_h[o];
            size_t idx = (size_t)b * DH + j0 + jj;
            ob[idx] = v;
            if (dup) ob2[idx] = v;
        }
    }
}

// ---------------- launch ----------------
extern "C" void kernel_launch(void* const* d_in, const int* in_sizes, int n_in,
                              void* d_out, int out_size) {
    const float* x      = (const float*)d_in[0];  // [T][B][DIN]
    const float* state0 = (const float*)d_in[1];  // [1][B][DH]
    const float* Wx     = (const float*)d_in[2];  // [DIN][DH]
    const float* Wh     = (const float*)d_in[3];  // [DH][DH]
    const float* bias   = (const float*)d_in[4];  // [DH]
    float* out = (float*)d_out;

    static bool attr_set = false;
    if (!attr_set) {
        cudaFuncSetAttribute(rnn_persistent_kernel,
                             cudaFuncAttributeMaxDynamicSharedMemorySize, SMEM_BYTES);
        attr_set = true;
    }

    // XP = X @ Wx + bias
    {
        float* xp;
        cudaGetSymbolAddress((void**)&xp, g_xp);
        dim3 grid(DH / GM_BN, (T_STEPS * B_DIM) / GM_BM);
        xw_gemm_kernel<<<grid, 256>>>(x, Wx, bias, xp);
    }
    // persistent recurrence
    rnn_persistent_kernel<<<NCTA, NTHREADS, SMEM_BYTES>>>(state0, Wh, out, out_size);
}

// round 12
// speedup vs baseline: 2.4626x; 1.0413x over previous
#include <cuda_runtime.h>
#include <math.h>

#define T_STEPS 512
#define B_DIM   64
#define DIN     1024
#define DH      1024
#define BN_EPS  1e-5f

#define NCTA        128
#define COLS_PER_CTA 8     // 1024 / 128
#define NTHREADS    1024   // 32 warps: 16 recurrence (R) + 16 input-gemm (G)
#define NRWARPS     16
#define K_PER_WARP  64     // 1024 / 16 (both R and G split-K over 16 warps)

// dynamic smem layout (floats):
//   s_wh    [1024*8] = 8192    Wh slab for this CTA's 8 columns
//   s_wx    [1024*8] = 8192    Wx slab
//   s_rpart [16*512] = 8192    recurrent split-K partials
//   s_gpart [2][16*512]=16384  input-gemm partials, double buffered
//   s_h     [512]              h / normalized values
//   s_bias  [8]
#define OFF_WH    0
#define OFF_WX    8192
#define OFF_RPART 16384
#define OFF_GPART 24576
#define OFF_H     40960
#define OFF_BIAS  41472
#define SMEM_FLOATS 41480
#define SMEM_BYTES  (SMEM_FLOATS * 4)

// ---------------- scratch (no cudaMalloc allowed) ----------------
__device__ float g_xt[(size_t)T_STEPS * DIN * B_DIM];  // XT[t][k][b]
__device__ float g_stateT[2][DH * B_DIM];              // [j][b] transposed state, double buffered
__device__ unsigned int g_bar_count = 0;
__device__ volatile unsigned int g_bar_gen = 0;

// ---------------- software grid barrier (all CTAs resident) ----------------
__device__ __forceinline__ void grid_barrier(unsigned int nblocks) {
    __syncthreads();
    if (threadIdx.x == 0) {
        __threadfence();                       // release my CTA's global writes
        unsigned int gen = g_bar_gen;
        if (atomicAdd(&g_bar_count, 1u) == nblocks - 1u) {
            atomicExch(&g_bar_count, 0u);
            __threadfence();
            g_bar_gen = gen + 1u;
        } else {
            while (g_bar_gen == gen) { }
        }
        __threadfence();                       // acquire
    }
    __syncthreads();
}

// ---------------- kernel 0: XT[t][k][b] = X[t][b][k] ----------------
__global__ void __launch_bounds__(256) transpose_x_kernel(
    const float* __restrict__ X,   // [T][B][DIN]
    float* __restrict__ XT)        // [T][DIN][B]
{
    __shared__ float tile[32][33];
    const int tx = threadIdx.x;          // 0..31
    const int ty = threadIdx.y;          // 0..7
    const int kt = blockIdx.x * 32;
    const int bt = blockIdx.y * 32;
    const int t  = blockIdx.z;

    const float* src = X + ((size_t)t * B_DIM + bt) * DIN + kt;
#pragma unroll
    for (int i = 0; i < 32; i += 8)
        tile[ty + i][tx] = src[(size_t)(ty + i) * DIN + tx];   // tile[b_local][k_local]
    __syncthreads();

    float* dst = XT + ((size_t)t * DIN + kt) * B_DIM + bt;
#pragma unroll
    for (int i = 0; i < 32; i += 8)
        dst[(size_t)(ty + i) * B_DIM + tx] = tile[tx][ty + i]; // XT[k][b]
}

// ---------------- G-warp body: xp partials for timestep tt ----------------
__device__ __forceinline__ void g_compute(
    const float* __restrict__ xt_t,   // g_xt + tt*DIN*B_DIM  :: [k][b]
    const float* __restrict__ s_wx,   // [k][8]
    float* __restrict__ s_gp,         // gpart buffer [16][512]
    int gw, int lane)
{
    float acc[8][2];
#pragma unroll
    for (int j = 0; j < 8; j++) { acc[j][0] = 0.0f; acc[j][1] = 0.0f; }

    const int b0 = lane * 2;
    const int k0 = gw * K_PER_WARP;
#pragma unroll 8
    for (int k = k0; k < k0 + K_PER_WARP; k++) {
        float2 xv = __ldg((const float2*)(xt_t + (size_t)k * B_DIM + b0));
        float4 wA = *(const float4*)&s_wx[k * 8];
        float4 wB = *(const float4*)&s_wx[k * 8 + 4];
        acc[0][0] += wA.x * xv.x;  acc[0][1] += wA.x * xv.y;
        acc[1][0] += wA.y * xv.x;  acc[1][1] += wA.y * xv.y;
        acc[2][0] += wA.z * xv.x;  acc[2][1] += wA.z * xv.y;
        acc[3][0] += wA.w * xv.x;  acc[3][1] += wA.w * xv.y;
        acc[4][0] += wB.x * xv.x;  acc[4][1] += wB.x * xv.y;
        acc[5][0] += wB.y * xv.x;  acc[5][1] += wB.y * xv.y;
        acc[6][0] += wB.z * xv.x;  acc[6][1] += wB.z * xv.y;
        acc[7][0] += wB.w * xv.x;  acc[7][1] += wB.w * xv.y;
    }
    float4* dst = (float4*)&s_gp[gw * 512 + lane * 16];
    const float4* srcv = (const float4*)acc;
#pragma unroll
    for (int q = 0; q < 4; q++) dst[q] = srcv[q];
}

// ---------------- kernel 1: fused persistent recurrence + input gemm ----------------
__global__ void __launch_bounds__(NTHREADS, 1) rnn_fused_kernel(
    const float* __restrict__ state0,  // [1][B][DH]  (b-major)
    const float* __restrict__ Wh,      // [DH][DH]
    const float* __restrict__ Wx,      // [DIN][DH]
    const float* __restrict__ bias,    // [DH]
    float* __restrict__ out,           // [2*T*B*DH] or [T*B*DH]
    int out_elems)
{
    extern __shared__ float smem[];
    float* s_wh    = smem + OFF_WH;
    float* s_wx    = smem + OFF_WX;
    float* s_rpart = smem + OFF_RPART;
    float* s_gpart = smem + OFF_GPART;   // [2][16*512]
    float* s_h     = smem + OFF_H;
    float* s_bias  = smem + OFF_BIAS;

    const int cta  = blockIdx.x;
    const int tid  = threadIdx.x;
    const int warp = tid >> 5;
    const int lane = tid & 31;
    const int j0   = cta * COLS_PER_CTA;

    // ---- stage weight slabs (ONCE): Wh[:,j0..j0+7] and Wx[:,j0..j0+7] ----
    for (int i = tid; i < 2048; i += NTHREADS) {
        int k = i >> 1;
        int h = (i & 1) * 4;
        *(float4*)&s_wh[k * 8 + h] = __ldg((const float4*)(Wh + (size_t)k * DH + j0 + h));
        *(float4*)&s_wx[k * 8 + h] = __ldg((const float4*)(Wx + (size_t)k * DH + j0 + h));
    }
    if (tid < 8) s_bias[tid] = bias[j0 + tid];

    // init transposed state buffer 0 for our columns
    for (int o = tid; o < 512; o += NTHREADS) {
        int jj = o >> 6;
        int b  = o & 63;
        g_stateT[0][(j0 + jj) * B_DIM + b] = state0[(size_t)b * DH + j0 + jj];
    }
    __syncthreads();   // smem slabs ready

    // ---- bootstrap: G-warps compute xp partials for t=0 into buffer 0 ----
    if (warp >= NRWARPS) {
        g_compute(g_xt, s_wx, s_gpart + 0 * 8192, warp - NRWARPS, lane);
    }

    const long long half = (long long)T_STEPS * B_DIM * DH;
    const bool dup = ((long long)out_elems >= 2 * half);

    for (int t = 0; t < T_STEPS; t++) {
        grid_barrier(NCTA);   // state[t] (and init) globally visible; also syncs smem

        const float* st  = g_stateT[t & 1];
        float*       stn = g_stateT[(t + 1) & 1];

        if (warp < NRWARPS) {
            // ---- R-warps: recurrent GEMM partials ----
            float acc[8][2];
#pragma unroll
            for (int j = 0; j < 8; j++) { acc[j][0] = 0.0f; acc[j][1] = 0.0f; }

            const int b0 = lane * 2;
            const int k0 = warp * K_PER_WARP;
#pragma unroll 8
            for (int k = k0; k < k0 + K_PER_WARP; k++) {
                // state is rewritten every step by other SMs -> bypass L1
                float2 sv = __ldcg((const float2*)(st + (size_t)k * B_DIM + b0));
                float4 wA = *(const float4*)&s_wh[k * 8];
                float4 wB = *(const float4*)&s_wh[k * 8 + 4];
                acc[0][0] += wA.x * sv.x;  acc[0][1] += wA.x * sv.y;
                acc[1][0] += wA.y * sv.x;  acc[1][1] += wA.y * sv.y;
                acc[2][0] += wA.z * sv.x;  acc[2][1] += wA.z * sv.y;
                acc[3][0] += wA.w * sv.x;  acc[3][1] += wA.w * sv.y;
                acc[4][0] += wB.x * sv.x;  acc[4][1] += wB.x * sv.y;
                acc[5][0] += wB.y * sv.x;  acc[5][1] += wB.y * sv.y;
                acc[6][0] += wB.z * sv.x;  acc[6][1] += wB.z * sv.y;
                acc[7][0] += wB.w * sv.x;  acc[7][1] += wB.w * sv.y;
            }
            float4* dst = (float4*)&s_rpart[warp * 512 + lane * 16];
            const float4* srcv = (const float4*)acc;
#pragma unroll
            for (int q = 0; q < 4; q++) dst[q] = srcv[q];
        } else if (t + 1 < T_STEPS) {
            // ---- G-warps: xp partials for step t+1 into buffer (t+1)&1 ----
            g_compute(g_xt + (size_t)(t + 1) * DIN * B_DIM, s_wx,
                      s_gpart + ((t + 1) & 1) * 8192, warp - NRWARPS, lane);
        }
        __syncthreads();

        // ---- reduce 16 R + 16 G partials + bias, tanh : o = b*8 + jj ----
        if (tid < 512) {
            int o  = tid;
            int jj = o & 7;
            int b  = o >> 3;
            int pi = (b >> 1) * 16 + jj * 2 + (b & 1);
            const float* gp = s_gpart + (t & 1) * 8192;
            float z = s_bias[jj];
#pragma unroll
            for (int w = 0; w < NRWARPS; w++) z += s_rpart[w * 512 + pi];
#pragma unroll
            for (int w = 0; w < NRWARPS; w++) z += gp[w * 512 + pi];
            s_h[o] = tanhf(z);
        }
        __syncthreads();

        // ---- BatchNorm over batch dim: warp jj (<8) handles column j0+jj ----
        if (warp < 8) {
            int jj = warp;
            float v1 = s_h[lane * 8 + jj];
            float v2 = s_h[(lane + 32) * 8 + jj];
            float sm = v1 + v2;
            float sq = v1 * v1 + v2 * v2;
#pragma unroll
            for (int off = 16; off; off >>= 1) {
                sm += __shfl_xor_sync(0xFFFFFFFFu, sm, off);
                sq += __shfl_xor_sync(0xFFFFFFFFu, sq, off);
            }
            float mu   = sm * (1.0f / 64.0f);
            float var  = sq * (1.0f / 64.0f) - mu * mu;
            float rstd = rsqrtf(var + BN_EPS);
            float o1 = (v1 - mu) * rstd;
            float o2 = (v2 - mu) * rstd;
            // next state (transposed, coalesced per column)
            stn[(j0 + jj) * B_DIM + lane]      = o1;
            stn[(j0 + jj) * B_DIM + lane + 32] = o2;
            // keep normalized value for the output writer
            s_h[lane * 8 + jj]        = o1;
            s_h[(lane + 32) * 8 + jj] = o2;
        }
        __syncthreads();

        // ---- write outputs (both tuple copies) ----
        if (tid < 512) {
            int o  = tid;
            int jj = o & 7;
            int b  = o >> 3;
            float v = s_h[o];
            size_t idx = (size_t)b * DH + j0 + jj;
            float* ob  = out + (size_t)t * B_DIM * DH;
            ob[idx] = v;
            if (dup) (out + half + (size_t)t * B_DIM * DH)[idx] = v;
        }
    }
}

// ---------------- launch ----------------
extern "C" void kernel_launch(void* const* d_in, const int* in_sizes, int n_in,
                              void* d_out, int out_size) {
    const float* x      = (const float*)d_in[0];  // [T][B][DIN]
    const float* state0 = (const float*)d_in[1];  // [1][B][DH]
    const float* Wx     = (const float*)d_in[2];  // [DIN][DH]
    const float* Wh     = (const float*)d_in[3];  // [DH][DH]
    const float* bias   = (const float*)d_in[4];  // [DH]
    float* out = (float*)d_out;

    // not a stream op: executes immediately, legal during graph capture,
    // identical effect on every call (no static guard needed)
    cudaFuncSetAttribute(rnn_fused_kernel,
                         cudaFuncAttributeMaxDynamicSharedMemorySize, SMEM_BYTES);

    // XT = transpose(X) per timestep: [T][B][DIN] -> [T][DIN][B]
    {
        float* xt;
        cudaGetSymbolAddress((void**)&xt, g_xt);
        dim3 grid(DIN / 32, B_DIM / 32, T_STEPS);
        transpose_x_kernel<<<grid, dim3(32, 8)>>>(x, xt);
    }
    // fused persistent recurrence + streamed input GEMM
    rnn_fused_kernel<<<NCTA, NTHREADS, SMEM_BYTES>>>(state0, Wh, Wx, bias, out, out_size);
}

// round 13
// speedup vs baseline: 2.9592x; 1.2017x over previous
#include <cuda_runtime.h>
#include <math.h>

#define T_STEPS 512
#define B_DIM   64
#define DIN     1024
#define DH      1024
#define BN_EPS  1e-5f

#define NCTA        128
#define COLS_PER_CTA 8     // 1024 / 128
#define NTHREADS    1024   // 32 warps: 16 recurrence (R) + 16 input-gemm (G)
#define NRWARPS     16
#define K_PER_WARP  64     // 1024 / 16 (both R and G split-K over 16 warps)

// named barriers
#define BAR_SYNC(id, cnt)   asm volatile("bar.sync %0, %1;"   :: "r"(id), "r"(cnt) : "memory")
#define BAR_ARRIVE(id, cnt) asm volatile("bar.arrive %0, %1;" :: "r"(id), "r"(cnt) : "memory")
// id 1+p : gpart buf p FULL    (G arrives 512, R syncs 512, count 1024)
// id 3+p : gpart buf p CONSUMED(R arrives 512, G syncs 512, count 1024)
// id 5   : R-group internal    (count 512)

// dynamic smem layout (floats):
#define OFF_WH    0                    // [1024*8] Wh slab
#define OFF_WX    8192                 // [1024*8] Wx slab
#define OFF_RPART 16384                // [16*512] recurrent split-K partials
#define OFF_GPART 24576                // [2][16*512] input-gemm partials (ring)
#define OFF_H     40960                // [512] h / normalized values
#define OFF_BIAS  41472                // [8]
#define SMEM_FLOATS 41480
#define SMEM_BYTES  (SMEM_FLOATS * 4)

// ---------------- scratch (no cudaMalloc allowed) ----------------
__device__ float g_xt[(size_t)T_STEPS * DIN * B_DIM];  // XT[t][k][b]
__device__ float g_stateT[2][DH * B_DIM];              // [j][b] transposed state, double buffered
__device__ unsigned int g_bar_count = 0;
__device__ volatile unsigned int g_bar_gen = 0;

// ---------------- kernel 0: XT[t][k][b] = X[t][b][k] ----------------
__global__ void __launch_bounds__(256) transpose_x_kernel(
    const float* __restrict__ X,   // [T][B][DIN]
    float* __restrict__ XT)        // [T][DIN][B]
{
    __shared__ float tile[32][33];
    const int tx = threadIdx.x;          // 0..31
    const int ty = threadIdx.y;          // 0..7
    const int kt = blockIdx.x * 32;
    const int bt = blockIdx.y * 32;
    const int t  = blockIdx.z;

    const float* src = X + ((size_t)t * B_DIM + bt) * DIN + kt;
#pragma unroll
    for (int i = 0; i < 32; i += 8)
        tile[ty + i][tx] = src[(size_t)(ty + i) * DIN + tx];
    __syncthreads();

    float* dst = XT + ((size_t)t * DIN + kt) * B_DIM + bt;
#pragma unroll
    for (int i = 0; i < 32; i += 8)
        dst[(size_t)(ty + i) * B_DIM + tx] = tile[tx][ty + i];
}

// ---------------- G-warp body: xp partials for one timestep ----------------
__device__ __forceinline__ void g_compute(
    const float* __restrict__ xt_t,   // [k][b]
    const float* __restrict__ s_wx,   // [k][8]
    float* __restrict__ s_gp,         // [16][512]
    int gw, int lane)
{
    float acc[8][2];
#pragma unroll
    for (int j = 0; j < 8; j++) { acc[j][0] = 0.0f; acc[j][1] = 0.0f; }

    const int b0 = lane * 2;
    const int k0 = gw * K_PER_WARP;
#pragma unroll 8
    for (int k = k0; k < k0 + K_PER_WARP; k++) {
        float2 xv = __ldg((const float2*)(xt_t + (size_t)k * B_DIM + b0));
        float4 wA = *(const float4*)&s_wx[k * 8];
        float4 wB = *(const float4*)&s_wx[k * 8 + 4];
        acc[0][0] += wA.x * xv.x;  acc[0][1] += wA.x * xv.y;
        acc[1][0] += wA.y * xv.x;  acc[1][1] += wA.y * xv.y;
        acc[2][0] += wA.z * xv.x;  acc[2][1] += wA.z * xv.y;
        acc[3][0] += wA.w * xv.x;  acc[3][1] += wA.w * xv.y;
        acc[4][0] += wB.x * xv.x;  acc[4][1] += wB.x * xv.y;
        acc[5][0] += wB.y * xv.x;  acc[5][1] += wB.y * xv.y;
        acc[6][0] += wB.z * xv.x;  acc[6][1] += wB.z * xv.y;
        acc[7][0] += wB.w * xv.x;  acc[7][1] += wB.w * xv.y;
    }
    float4* dst = (float4*)&s_gp[gw * 512 + lane * 16];
    const float4* srcv = (const float4*)acc;
#pragma unroll
    for (int q = 0; q < 4; q++) dst[q] = srcv[q];
}

// ---------------- kernel 1: fused persistent recurrence + decoupled input gemm ----------------
__global__ void __launch_bounds__(NTHREADS, 1) rnn_fused_kernel(
    const float* __restrict__ state0,  // [1][B][DH]
    const float* __restrict__ Wh,      // [DH][DH]
    const float* __restrict__ Wx,      // [DIN][DH]
    const float* __restrict__ bias,    // [DH]
    float* __restrict__ out,
    int out_elems)
{
    extern __shared__ float smem[];
    float* s_wh    = smem + OFF_WH;
    float* s_wx    = smem + OFF_WX;
    float* s_rpart = smem + OFF_RPART;
    float* s_gpart = smem + OFF_GPART;   // [2][16*512]
    float* s_h     = smem + OFF_H;
    float* s_bias  = smem + OFF_BIAS;

    const int cta  = blockIdx.x;
    const int tid  = threadIdx.x;
    const int warp = tid >> 5;
    const int lane = tid & 31;
    const int j0   = cta * COLS_PER_CTA;

    // ---- stage weight slabs (ONCE) ----
    for (int i = tid; i < 2048; i += NTHREADS) {
        int k = i >> 1;
        int h = (i & 1) * 4;
        *(float4*)&s_wh[k * 8 + h] = __ldg((const float4*)(Wh + (size_t)k * DH + j0 + h));
        *(float4*)&s_wx[k * 8 + h] = __ldg((const float4*)(Wx + (size_t)k * DH + j0 + h));
    }
    if (tid < 8) s_bias[tid] = bias[j0 + tid];

    // init transposed state buffer 0 for our columns
    for (int o = tid; o < 512; o += NTHREADS) {
        int jj = o >> 6;
        int b  = o & 63;
        g_stateT[0][(j0 + jj) * B_DIM + b] = state0[(size_t)b * DH + j0 + jj];
    }
    __syncthreads();   // slabs + init ordered before both groups proceed

    const long long half = (long long)T_STEPS * B_DIM * DH;
    const bool dup = ((long long)out_elems >= 2 * half);

    if (warp >= NRWARPS) {
        // ================= G-warps: free-running producer =================
        const int gw = warp - NRWARPS;
        for (int tt = 0; tt < T_STEPS; tt++) {
            const int p = tt & 1;
            if (tt >= 2) BAR_SYNC(3 + p, 1024);          // buf p consumed (step tt-2)
            g_compute(g_xt + (size_t)tt * DIN * B_DIM, s_wx,
                      s_gpart + p * 8192, gw, lane);
            __threadfence_block();                        // drain STS before arrive
            BAR_ARRIVE(1 + p, 1024);                      // buf p full
        }
    } else {
        // ================= R-warps: recurrence + epilogue =================
        for (int t = 0; t < T_STEPS; t++) {
            // ---- grid barrier (R threads only) ----
            BAR_SYNC(5, 512);
            if (tid == 0) {
                __threadfence();
                unsigned int gen = g_bar_gen;
                if (atomicAdd(&g_bar_count, 1u) == NCTA - 1u) {
                    atomicExch(&g_bar_count, 0u);
                    __threadfence();
                    g_bar_gen = gen + 1u;
                } else {
                    while (g_bar_gen == gen) { }
                }
                __threadfence();
            }
            BAR_SYNC(5, 512);

            const float* st  = g_stateT[t & 1];
            float*       stn = g_stateT[(t + 1) & 1];

            // ---- recurrent GEMM partials ----
            {
                float acc[8][2];
#pragma unroll
                for (int j = 0; j < 8; j++) { acc[j][0] = 0.0f; acc[j][1] = 0.0f; }

                const int b0 = lane * 2;
                const int k0 = warp * K_PER_WARP;
#pragma unroll 8
                for (int k = k0; k < k0 + K_PER_WARP; k++) {
                    float2 sv = __ldcg((const float2*)(st + (size_t)k * B_DIM + b0));
                    float4 wA = *(const float4*)&s_wh[k * 8];
                    float4 wB = *(const float4*)&s_wh[k * 8 + 4];
                    acc[0][0] += wA.x * sv.x;  acc[0][1] += wA.x * sv.y;
                    acc[1][0] += wA.y * sv.x;  acc[1][1] += wA.y * sv.y;
                    acc[2][0] += wA.z * sv.x;  acc[2][1] += wA.z * sv.y;
                    acc[3][0] += wA.w * sv.x;  acc[3][1] += wA.w * sv.y;
                    acc[4][0] += wB.x * sv.x;  acc[4][1] += wB.x * sv.y;
                    acc[5][0] += wB.y * sv.x;  acc[5][1] += wB.y * sv.y;
                    acc[6][0] += wB.z * sv.x;  acc[6][1] += wB.z * sv.y;
                    acc[7][0] += wB.w * sv.x;  acc[7][1] += wB.w * sv.y;
                }
                float4* dst = (float4*)&s_rpart[warp * 512 + lane * 16];
                const float4* srcv = (const float4*)acc;
#pragma unroll
                for (int q = 0; q < 4; q++) dst[q] = srcv[q];
            }
            BAR_SYNC(5, 512);            // rpart ready (R group)
            BAR_SYNC(1 + (t & 1), 1024); // gpart[t] ready (usually zero wait)

            // ---- reduce 16R + 16G partials + bias, tanh ----
            const int o  = tid;          // 0..511
            const int jj = o & 7;
            const int b  = o >> 3;
            {
                const int pi = (b >> 1) * 16 + jj * 2 + (b & 1);
                const float* gp = s_gpart + (t & 1) * 8192;
                float z = s_bias[jj];
#pragma unroll
                for (int w = 0; w < NRWARPS; w++) z += s_rpart[w * 512 + pi];
#pragma unroll
                for (int w = 0; w < NRWARPS; w++) z += gp[w * 512 + pi];
                s_h[o] = tanhf(z);
            }
            BAR_SYNC(5, 512);            // s_h ready; all gpart reads complete
            BAR_ARRIVE(3 + (t & 1), 1024); // release gpart buf to G

            // ---- BatchNorm over batch dim: warps 0..7, column j0+jj ----
            if (warp < 8) {
                int c = warp;
                float v1 = s_h[lane * 8 + c];
                float v2 = s_h[(lane + 32) * 8 + c];
                float sm = v1 + v2;
                float sq = v1 * v1 + v2 * v2;
#pragma unroll
                for (int off = 16; off; off >>= 1) {
                    sm += __shfl_xor_sync(0xFFFFFFFFu, sm, off);
                    sq += __shfl_xor_sync(0xFFFFFFFFu, sq, off);
                }
                float mu   = sm * (1.0f / 64.0f);
                float var  = sq * (1.0f / 64.0f) - mu * mu;
                float rstd = rsqrtf(var + BN_EPS);
                float o1 = (v1 - mu) * rstd;
                float o2 = (v2 - mu) * rstd;
                stn[(j0 + c) * B_DIM + lane]      = o1;
                stn[(j0 + c) * B_DIM + lane + 32] = o2;
                s_h[lane * 8 + c]        = o1;
                s_h[(lane + 32) * 8 + c] = o2;
            }
            BAR_SYNC(5, 512);

            // ---- write outputs (both tuple copies) ----
            {
                float v = s_h[o];
                size_t idx = (size_t)b * DH + j0 + jj;
                float* ob = out + (size_t)t * B_DIM * DH;
                ob[idx] = v;
                if (dup) (out + half + (size_t)t * B_DIM * DH)[idx] = v;
            }
        }
    }
}

// ---------------- launch ----------------
extern "C" void kernel_launch(void* const* d_in, const int* in_sizes, int n_in,
                              void* d_out, int out_size) {
    const float* x      = (const float*)d_in[0];  // [T][B][DIN]
    const float* state0 = (const float*)d_in[1];  // [1][B][DH]
    const float* Wx     = (const float*)d_in[2];  // [DIN][DH]
    const float* Wh     = (const float*)d_in[3];  // [DH][DH]
    const float* bias   = (const float*)d_in[4];  // [DH]
    float* out = (float*)d_out;

    // immediate (non-stream) call: legal during capture, identical every call
    cudaFuncSetAttribute(rnn_fused_kernel,
                         cudaFuncAttributeMaxDynamicSharedMemorySize, SMEM_BYTES);

    // XT = transpose(X) per timestep: [T][B][DIN] -> [T][DIN][B]
    {
        float* xt;
        cudaGetSymbolAddress((void**)&xt, g_xt);
        dim3 grid(DIN / 32, B_DIM / 32, T_STEPS);
        transpose_x_kernel<<<grid, dim3(32, 8)>>>(x, xt);
    }
    // fused persistent recurrence + decoupled input GEMM
    rnn_fused_kernel<<<NCTA, NTHREADS, SMEM_BYTES>>>(state0, Wh, Wx, bias, out, out_size);
}

// round 14
// speedup vs baseline: 3.1481x; 1.0638x over previous
#include <cuda_runtime.h>
#include <math.h>

#define T_STEPS 512
#define B_DIM   64
#define DIN     1024
#define DH      1024
#define BN_EPS  1e-5f

#define NCTA        128
#define COLS_PER_CTA 8     // 1024 / 128
#define NTHREADS    1024   // 32 warps: 16 recurrence (R) + 16 input-gemm (G)
#define NRWARPS     16
#define K_PER_WARP  64     // 1024 / 16

// named barriers
#define BAR_SYNC(id, cnt)   asm volatile("bar.sync %0, %1;"   :: "r"(id), "r"(cnt) : "memory")
#define BAR_ARRIVE(id, cnt) asm volatile("bar.arrive %0, %1;" :: "r"(id), "r"(cnt) : "memory")
// id 1+p : gpart buf p FULL     (G arrives 512, R syncs 512, count 1024)
// id 3+p : gpart buf p CONSUMED (R arrives 512, G syncs 512, count 1024)
// id 5   : R-group internal     (count 512)

// packed fp32x2 ops (sm_100+; ptxas never auto-generates these)
#define FMA_F32X2(d, a, b, c) \
    asm("fma.rn.f32x2 %0, %1, %2, %3;" : "=l"(d) : "l"(a), "l"(b), "l"(c))
#define DUP_F32X2(out, f) \
    asm("mov.b64 %0, {%1, %1};" : "=l"(out) : "r"(__float_as_uint(f)))

// dynamic smem layout (floats):
#define OFF_WH    0                    // [1024*8] Wh slab
#define OFF_WX    8192                 // [1024*8] Wx slab
#define OFF_RPART 16384                // [16*512] recurrent split-K partials
#define OFF_GPART 24576                // [2][16*512] input-gemm partials (ring)
#define OFF_H     40960                // [512] h / normalized values
#define OFF_BIAS  41472                // [8]
#define SMEM_FLOATS 41480
#define SMEM_BYTES  (SMEM_FLOATS * 4)

// ---------------- scratch (no cudaMalloc allowed) ----------------
__device__ float g_xt[(size_t)T_STEPS * DIN * B_DIM];  // XT[t][k][b]
__device__ float g_stateT[2][DH * B_DIM];              // [j][b] transposed state, double buffered
__device__ unsigned int g_bar_count = 0;
__device__ volatile unsigned int g_bar_gen = 0;

// ---------------- kernel 0: XT[t][k][b] = X[t][b][k] ----------------
__global__ void __launch_bounds__(256) transpose_x_kernel(
    const float* __restrict__ X,   // [T][B][DIN]
    float* __restrict__ XT)        // [T][DIN][B]
{
    __shared__ float tile[32][33];
    const int tx = threadIdx.x;
    const int ty = threadIdx.y;
    const int kt = blockIdx.x * 32;
    const int bt = blockIdx.y * 32;
    const int t  = blockIdx.z;

    const float* src = X + ((size_t)t * B_DIM + bt) * DIN + kt;
#pragma unroll
    for (int i = 0; i < 32; i += 8)
        tile[ty + i][tx] = src[(size_t)(ty + i) * DIN + tx];
    __syncthreads();

    float* dst = XT + ((size_t)t * DIN + kt) * B_DIM + bt;
#pragma unroll
    for (int i = 0; i < 32; i += 8)
        dst[(size_t)(ty + i) * B_DIM + tx] = tile[tx][ty + i];
}

// ---------------- shared GEMM inner body (FFMA2), for R and G warps ----------------
// acc[bb*4+p] is f32x2 over columns {2p, 2p+1}, batch b0+bb.
// partial store order: float layout [lane*16 + bb*8 + j]  (j = 0..7)
__device__ __forceinline__ void gemm_body_f32x2(
    const float* __restrict__ vecT,   // [k][b] operand (state or xt), L2-coherent reads
    const float* __restrict__ s_w,    // [k][8] weight slab (smem)
    float* __restrict__ s_p,          // [16][512] partial buffer (smem)
    int kw, int lane, bool bypassL1)
{
    unsigned long long acc[8];
#pragma unroll
    for (int i = 0; i < 8; i++) acc[i] = 0ULL;

    const int b0 = lane * 2;
    const int k0 = kw * K_PER_WARP;
#pragma unroll 8
    for (int k = k0; k < k0 + K_PER_WARP; k++) {
        float2 sv = bypassL1 ? __ldcg((const float2*)(vecT + (size_t)k * B_DIM + b0))
                             : __ldg ((const float2*)(vecT + (size_t)k * B_DIM + b0));
        unsigned long long sx, sy;
        DUP_F32X2(sx, sv.x);
        DUP_F32X2(sy, sv.y);
        ulonglong2 w01 = *(const ulonglong2*)&s_w[k * 8];      // col pairs {0,1},{2,3}
        ulonglong2 w23 = *(const ulonglong2*)&s_w[k * 8 + 4];  // col pairs {4,5},{6,7}
        FMA_F32X2(acc[0], w01.x, sx, acc[0]);
        FMA_F32X2(acc[1], w01.y, sx, acc[1]);
        FMA_F32X2(acc[2], w23.x, sx, acc[2]);
        FMA_F32X2(acc[3], w23.y, sx, acc[3]);
        FMA_F32X2(acc[4], w01.x, sy, acc[4]);
        FMA_F32X2(acc[5], w01.y, sy, acc[5]);
        FMA_F32X2(acc[6], w23.x, sy, acc[6]);
        FMA_F32X2(acc[7], w23.y, sy, acc[7]);
    }
    // contiguous u64 stores give float layout bb*8 + 2p{lo,hi} = bb*8 + j
    ulonglong2* dst = (ulonglong2*)&s_p[kw * 512 + lane * 16];
#pragma unroll
    for (int q = 0; q < 4; q++) {
        ulonglong2 v; v.x = acc[2 * q]; v.y = acc[2 * q + 1];
        dst[q] = v;
    }
}

// ---------------- kernel 1: fused persistent recurrence + decoupled input gemm ----------------
__global__ void __launch_bounds__(NTHREADS, 1) rnn_fused_kernel(
    const float* __restrict__ state0,  // [1][B][DH]
    const float* __restrict__ Wh,      // [DH][DH]
    const float* __restrict__ Wx,      // [DIN][DH]
    const float* __restrict__ bias,    // [DH]
    float* __restrict__ out,
    int out_elems)
{
    extern __shared__ float smem[];
    float* s_wh    = smem + OFF_WH;
    float* s_wx    = smem + OFF_WX;
    float* s_rpart = smem + OFF_RPART;
    float* s_gpart = smem + OFF_GPART;   // [2][16*512]
    float* s_h     = smem + OFF_H;
    float* s_bias  = smem + OFF_BIAS;

    const int cta  = blockIdx.x;
    const int tid  = threadIdx.x;
    const int warp = tid >> 5;
    const int lane = tid & 31;
    const int j0   = cta * COLS_PER_CTA;

    // ---- stage weight slabs (ONCE) ----
    for (int i = tid; i < 2048; i += NTHREADS) {
        int k = i >> 1;
        int h = (i & 1) * 4;
        *(float4*)&s_wh[k * 8 + h] = __ldg((const float4*)(Wh + (size_t)k * DH + j0 + h));
        *(float4*)&s_wx[k * 8 + h] = __ldg((const float4*)(Wx + (size_t)k * DH + j0 + h));
    }
    if (tid < 8) s_bias[tid] = bias[j0 + tid];

    // init transposed state buffer 0 for our columns
    for (int o = tid; o < 512; o += NTHREADS) {
        int jj = o >> 6;
        int b  = o & 63;
        g_stateT[0][(j0 + jj) * B_DIM + b] = state0[(size_t)b * DH + j0 + jj];
    }
    __syncthreads();

    const long long half = (long long)T_STEPS * B_DIM * DH;
    const bool dup = ((long long)out_elems >= 2 * half);

    if (warp >= NRWARPS) {
        // ================= G-warps: free-running producer =================
        const int gw = warp - NRWARPS;
        for (int tt = 0; tt < T_STEPS; tt++) {
            const int p = tt & 1;
            if (tt >= 2) BAR_SYNC(3 + p, 1024);          // buf p consumed (step tt-2)
            gemm_body_f32x2(g_xt + (size_t)tt * DIN * B_DIM, s_wx,
                            s_gpart + p * 8192, gw, lane, false);
            __threadfence_block();                        // drain STS before arrive
            BAR_ARRIVE(1 + p, 1024);                      // buf p full
        }
    } else {
        // ================= R-warps: recurrence + epilogue =================
        for (int t = 0; t < T_STEPS; t++) {
            // ---- grid barrier (R threads only) ----
            BAR_SYNC(5, 512);
            if (tid == 0) {
                __threadfence();
                unsigned int gen = g_bar_gen;
                if (atomicAdd(&g_bar_count, 1u) == NCTA - 1u) {
                    atomicExch(&g_bar_count, 0u);
                    __threadfence();
                    g_bar_gen = gen + 1u;
                } else {
                    while (g_bar_gen == gen) { }
                }
                __threadfence();
            }
            BAR_SYNC(5, 512);

            const float* st  = g_stateT[t & 1];
            float*       stn = g_stateT[(t + 1) & 1];

            // ---- recurrent GEMM partials (FFMA2) ----
            gemm_body_f32x2(st, s_wh, s_rpart, warp, lane, true);

            BAR_SYNC(5, 512);            // rpart ready (R group)
            BAR_SYNC(1 + (t & 1), 1024); // gpart[t] ready (usually zero wait)

            // ---- reduce 16R + 16G partials + bias, tanh ----
            const int o  = tid;          // 0..511
            const int jj = o & 7;
            const int b  = o >> 3;
            {
                const int pi = (b >> 1) * 16 + (b & 1) * 8 + jj;
                const float* gp = s_gpart + (t & 1) * 8192;
                float z = s_bias[jj];
#pragma unroll
                for (int w = 0; w < NRWARPS; w++) z += s_rpart[w * 512 + pi];
#pragma unroll
                for (int w = 0; w < NRWARPS; w++) z += gp[w * 512 + pi];
                s_h[o] = tanhf(z);
            }
            BAR_SYNC(5, 512);            // s_h ready; gpart reads complete
            BAR_ARRIVE(3 + (t & 1), 1024); // release gpart buf to G

            // ---- BatchNorm over batch dim: warps 0..7, column j0+c ----
            if (warp < 8) {
                int c = warp;
                float v1 = s_h[lane * 8 + c];
                float v2 = s_h[(lane + 32) * 8 + c];
                float sm = v1 + v2;
                float sq = v1 * v1 + v2 * v2;
#pragma unroll
                for (int off = 16; off; off >>= 1) {
                    sm += __shfl_xor_sync(0xFFFFFFFFu, sm, off);
                    sq += __shfl_xor_sync(0xFFFFFFFFu, sq, off);
                }
                float mu   = sm * (1.0f / 64.0f);
                float var  = sq * (1.0f / 64.0f) - mu * mu;
                float rstd = rsqrtf(var + BN_EPS);
                float o1 = (v1 - mu) * rstd;
                float o2 = (v2 - mu) * rstd;
                stn[(j0 + c) * B_DIM + lane]      = o1;
                stn[(j0 + c) * B_DIM + lane + 32] = o2;
                s_h[lane * 8 + c]        = o1;
                s_h[(lane + 32) * 8 + c] = o2;
            }
            BAR_SYNC(5, 512);

            // ---- write outputs (both tuple copies) ----
            {
                float v = s_h[o];
                size_t idx = (size_t)b * DH + j0 + jj;
                float* ob = out + (size_t)t * B_DIM * DH;
                ob[idx] = v;
                if (dup) (out + half + (size_t)t * B_DIM * DH)[idx] = v;
            }
        }
    }
}

// ---------------- launch ----------------
extern "C" void kernel_launch(void* const* d_in, const int* in_sizes, int n_in,
                              void* d_out, int out_size) {
    const float* x      = (const float*)d_in[0];  // [T][B][DIN]
    const float* state0 = (const float*)d_in[1];  // [1][B][DH]
    const float* Wx     = (const float*)d_in[2];  // [DIN][DH]
    const float* Wh     = (const float*)d_in[3];  // [DH][DH]
    const float* bias   = (const float*)d_in[4];  // [DH]
    float* out = (float*)d_out;

    // immediate (non-stream) call: legal during capture, identical every call
    cudaFuncSetAttribute(rnn_fused_kernel,
                         cudaFuncAttributeMaxDynamicSharedMemorySize, SMEM_BYTES);

    // XT = transpose(X) per timestep: [T][B][DIN] -> [T][DIN][B]
    {
        float* xt;
        cudaGetSymbolAddress((void**)&xt, g_xt);
        dim3 grid(DIN / 32, B_DIM / 32, T_STEPS);
        transpose_x_kernel<<<grid, dim3(32, 8)>>>(x, xt);
    }
    // fused persistent recurrence + decoupled input GEMM (FFMA2 inner loops)
    rnn_fused_kernel<<<NCTA, NTHREADS, SMEM_BYTES>>>(state0, Wh, Wx, bias, out, out_size);
}